// round 14
// baseline (speedup 1.0000x reference)
#include <cuda_runtime.h>
#include <cuda_bf16.h>
#include <cstdint>

#define BATCH 8
#define SEQ   2048
#define DIM   512

// Scratch
__device__ float g_M[BATCH * DIM * DIM];    // M = K^T V   [b][i][j]   8 MiB
__device__ float g_Qt[BATCH * DIM * SEQ];   // Q^T         [b][i][q]  32 MiB
__device__ int g_vlen_is64;

// Interleaved (h,l) smem geometry. A tile: 32 k-rows x 128 m (256 floats+pad),
// B tile: 32 k-rows x 64 n (128 floats+pad). pads % 32 == 8 -> conflict-free
// fragment LDS.64 (bank = 8q + 2g law, proven R12).
#define PADA 264
#define PADB 136
#define AFLOATS (32 * PADA)        // 8448
#define BFLOATS (32 * PADB)        // 4352
#define BUFF    (AFLOATS + BFLOATS)
#define DYN_SMEM (2 * BUFF * 4)    // 102400 B -> 2 CTAs/SM (204.8KB < 227KB)

// ---------------------------------------------------------------------------
// tf32 helpers. Truncation split: h = x & 0xFFFFE000 (exact tf32 bits),
// l = x - h exact in fp32.
// ---------------------------------------------------------------------------
__device__ __forceinline__ float tr19(float x) {
    return __uint_as_float(__float_as_uint(x) & 0xFFFFE000u);
}

__device__ __forceinline__ void mma_tf32(float* c, const uint32_t* a, const uint32_t* b) {
    asm volatile(
        "mma.sync.aligned.m16n8k8.row.col.f32.tf32.tf32.f32 "
        "{%0,%1,%2,%3}, {%4,%5,%6,%7}, {%8,%9}, {%0,%1,%2,%3};"
        : "+f"(c[0]), "+f"(c[1]), "+f"(c[2]), "+f"(c[3])
        : "r"(a[0]), "r"(a[1]), "r"(a[2]), "r"(a[3]), "r"(b[0]), "r"(b[1]));
}

// ---------------------------------------------------------------------------
// valid_len dtype detector (int64 vs int32) — proven R4
// ---------------------------------------------------------------------------
__global__ void detect_vlen_kernel(const unsigned long long* __restrict__ v) {
    __shared__ int bad;
    if (threadIdx.x == 0) bad = 0;
    __syncthreads();
    for (int i = threadIdx.x; i < 1024; i += blockDim.x)
        if (v[i] >= 512ull) atomicOr(&bad, 1);
    __syncthreads();
    if (threadIdx.x == 0) g_vlen_is64 = bad ? 0 : 1;
}

// ---------------------------------------------------------------------------
// Q transpose: Q [B,SEQ,DIM] -> g_Qt [B,DIM,SEQ]  (32x32 smem tiles) — proven
// ---------------------------------------------------------------------------
__global__ __launch_bounds__(256) void transposeQ_kernel(const float* __restrict__ Q) {
    __shared__ float tile[32][33];
    const int b = blockIdx.z;
    const int s0 = blockIdx.x * 32, d0 = blockIdx.y * 32;
    const int tx = threadIdx.x, ty = threadIdx.y;  // (32, 8)
    const float* src = Q + ((size_t)b * SEQ + s0) * DIM + d0;
#pragma unroll
    for (int i = 0; i < 4; i++)
        tile[ty + 8 * i][tx] = src[(size_t)(ty + 8 * i) * DIM + tx];
    __syncthreads();
    float* dst = g_Qt + ((size_t)b * DIM + d0) * SEQ + s0;
#pragma unroll
    for (int i = 0; i < 4; i++)
        dst[(size_t)(ty + 8 * i) * SEQ + tx] = tile[tx][ty + 8 * i];
}

// ===========================================================================
// GEMM body macro (plain kernels — R8 lesson; dyn smem + attr — R7 proven).
//   D[m][n] = sum_k A[k][m]*B[k][n], tf32 split products hh + hl + lh.
//   CTA tile 128m x 64n, 256 threads, 8 warps (4m x 2n) of 32x32.
//   2 CTAs/SM: independent barriers/pipelines hide each other's bubbles.
//   Double-buffered; (h,l) interleaved floats => frag = LDS.64, no inner ALU.
// ===========================================================================
#define GEMM_BODY(NCHUNK, LDA, LDB, EPILOGUE)                                  \
    extern __shared__ float sm[];                                              \
    const int t = threadIdx.x;                                                 \
    const int wid = t >> 5, lane = t & 31;                                     \
    const int g = lane >> 2, q = lane & 3;                                     \
    const int mw = (wid >> 1) * 32;                                            \
    const int nw = (wid & 1) * 32;                                             \
    const int b = blockIdx.z;                                                  \
    const int m0 = blockIdx.y * 128;                                           \
    const int n0 = blockIdx.x * 64;                                            \
    float acc[2][4][4] = {};                                                   \
    const int fr = t >> 3, f8 = t & 7;                                         \
    float2 pa[8], pb[4];                                                       \
    /* LDG chunk 0 */                                                          \
    _Pragma("unroll")                                                          \
    for (int u = 0; u < 8; u++)                                                \
        pa[u] = *(const float2*)&Ab[(size_t)fr * (LDA) + m0 + 2 * f8 + 16 * u]; \
    _Pragma("unroll")                                                          \
    for (int u = 0; u < 4; u++)                                                \
        pb[u] = *(const float2*)&Bb[(size_t)fr * (LDB) + n0 + 2 * f8 + 16 * u]; \
    /* split + STS buffer 0 */                                                 \
    {                                                                          \
        float* Asm = sm;                                                       \
        float* Bsm = sm + AFLOATS;                                             \
        _Pragma("unroll")                                                      \
        for (int u = 0; u < 8; u++) {                                          \
            float h0 = tr19(pa[u].x), h1 = tr19(pa[u].y);                      \
            *(float4*)&Asm[fr * PADA + 4 * f8 + 32 * u] =                      \
                make_float4(h0, pa[u].x - h0, h1, pa[u].y - h1);               \
        }                                                                      \
        _Pragma("unroll")                                                      \
        for (int u = 0; u < 4; u++) {                                          \
            float h0 = tr19(pb[u].x), h1 = tr19(pb[u].y);                      \
            *(float4*)&Bsm[fr * PADB + 4 * f8 + 32 * u] =                      \
                make_float4(h0, pb[u].x - h0, h1, pb[u].y - h1);               \
        }                                                                      \
    }                                                                          \
    __syncthreads();                                                           \
    for (int c = 0; c < (NCHUNK); c++) {                                       \
        if (c + 1 < (NCHUNK)) {                                                \
            const int kn = (c + 1) * 32;                                       \
            _Pragma("unroll")                                                  \
            for (int u = 0; u < 8; u++)                                        \
                pa[u] = *(const float2*)&Ab[(size_t)(kn + fr) * (LDA) + m0 + 2 * f8 + 16 * u]; \
            _Pragma("unroll")                                                  \
            for (int u = 0; u < 4; u++)                                        \
                pb[u] = *(const float2*)&Bb[(size_t)(kn + fr) * (LDB) + n0 + 2 * f8 + 16 * u]; \
        }                                                                      \
        const float* Asm = sm + (c & 1) * BUFF;                                \
        const float* Bsm = Asm + AFLOATS;                                      \
        _Pragma("unroll")                                                      \
        for (int kk = 0; kk < 4; kk++) {                                       \
            uint32_t bh[8], bl[8];                                             \
            _Pragma("unroll")                                                  \
            for (int nt = 0; nt < 4; nt++) {                                   \
                float2 v0 = *(const float2*)&Bsm[(kk * 8 + q) * PADB + 2 * (nw + nt * 8 + g)]; \
                float2 v1 = *(const float2*)&Bsm[(kk * 8 + q + 4) * PADB + 2 * (nw + nt * 8 + g)]; \
                bh[nt * 2]     = __float_as_uint(v0.x);                        \
                bl[nt * 2]     = __float_as_uint(v0.y);                        \
                bh[nt * 2 + 1] = __float_as_uint(v1.x);                        \
                bl[nt * 2 + 1] = __float_as_uint(v1.y);                        \
            }                                                                  \
            uint32_t ah[2][4], al[2][4];                                       \
            _Pragma("unroll")                                                  \
            for (int mt = 0; mt < 2; mt++) {                                   \
                const int ma = mw + mt * 16 + g;                               \
                float2 w0 = *(const float2*)&Asm[(kk * 8 + q) * PADA + 2 * ma];          \
                float2 w1 = *(const float2*)&Asm[(kk * 8 + q) * PADA + 2 * (ma + 8)];    \
                float2 w2 = *(const float2*)&Asm[(kk * 8 + q + 4) * PADA + 2 * ma];      \
                float2 w3 = *(const float2*)&Asm[(kk * 8 + q + 4) * PADA + 2 * (ma + 8)]; \
                ah[mt][0] = __float_as_uint(w0.x); al[mt][0] = __float_as_uint(w0.y); \
                ah[mt][1] = __float_as_uint(w1.x); al[mt][1] = __float_as_uint(w1.y); \
                ah[mt][2] = __float_as_uint(w2.x); al[mt][2] = __float_as_uint(w2.y); \
                ah[mt][3] = __float_as_uint(w3.x); al[mt][3] = __float_as_uint(w3.y); \
            }                                                                  \
            _Pragma("unroll")                                                  \
            for (int mt = 0; mt < 2; mt++)                                     \
                _Pragma("unroll")                                              \
                for (int nt = 0; nt < 4; nt++)                                 \
                    mma_tf32(acc[mt][nt], ah[mt], &bh[nt * 2]);                \
            _Pragma("unroll")                                                  \
            for (int mt = 0; mt < 2; mt++)                                     \
                _Pragma("unroll")                                              \
                for (int nt = 0; nt < 4; nt++)                                 \
                    mma_tf32(acc[mt][nt], ah[mt], &bl[nt * 2]);                \
            _Pragma("unroll")                                                  \
            for (int mt = 0; mt < 2; mt++)                                     \
                _Pragma("unroll")                                              \
                for (int nt = 0; nt < 4; nt++)                                 \
                    mma_tf32(acc[mt][nt], al[mt], &bh[nt * 2]);                \
        }                                                                      \
        if (c + 1 < (NCHUNK)) {                                                \
            float* Adst = sm + ((c + 1) & 1) * BUFF;                           \
            float* Bdst = Adst + AFLOATS;                                      \
            _Pragma("unroll")                                                  \
            for (int u = 0; u < 8; u++) {                                      \
                float h0 = tr19(pa[u].x), h1 = tr19(pa[u].y);                  \
                *(float4*)&Adst[fr * PADA + 4 * f8 + 32 * u] =                 \
                    make_float4(h0, pa[u].x - h0, h1, pa[u].y - h1);           \
            }                                                                  \
            _Pragma("unroll")                                                  \
            for (int u = 0; u < 4; u++) {                                      \
                float h0 = tr19(pb[u].x), h1 = tr19(pb[u].y);                  \
                *(float4*)&Bdst[fr * PADB + 4 * f8 + 32 * u] =                 \
                    make_float4(h0, pb[u].x - h0, h1, pb[u].y - h1);           \
            }                                                                  \
        }                                                                      \
        __syncthreads();                                                       \
    }                                                                          \
    _Pragma("unroll")                                                          \
    for (int mt = 0; mt < 2; mt++) {                                           \
        _Pragma("unroll")                                                      \
        for (int nt = 0; nt < 4; nt++) {                                       \
            const int m = m0 + mw + mt * 16 + g;                               \
            const int n = n0 + nw + nt * 8 + 2 * q;                            \
            EPILOGUE                                                           \
        }                                                                      \
    }

// ---------------------------------------------------------------------------
// gemmA: M[i][j] = sum_s K[s][i] V[s][j]    (K=2048)
// ---------------------------------------------------------------------------
__global__ __launch_bounds__(256, 2) void gemmA_tf32(const float* __restrict__ Kg,
                                                     const float* __restrict__ Vg) {
    const float* Ab = Kg + (size_t)blockIdx.z * SEQ * DIM;
    const float* Bb = Vg + (size_t)blockIdx.z * SEQ * DIM;
    GEMM_BODY(SEQ / 32, DIM, DIM, {
        float* dst = g_M + (size_t)b * DIM * DIM + (size_t)m * DIM + n;
        *(float2*)dst = make_float2(acc[mt][nt][0], acc[mt][nt][1]);
        *(float2*)(dst + 8 * DIM) = make_float2(acc[mt][nt][2], acc[mt][nt][3]);
    })
}

// ---------------------------------------------------------------------------
// gemmB: X[q][j] = sum_i Qt[i][q] M[i][j] / sqrt(512)   (K=512)
// ---------------------------------------------------------------------------
__global__ __launch_bounds__(256, 2) void gemmB_tf32(float* __restrict__ Og) {
    const float* Ab = g_Qt + (size_t)blockIdx.z * DIM * SEQ;
    const float* Bb = g_M + (size_t)blockIdx.z * DIM * DIM;
    GEMM_BODY(DIM / 32, SEQ, DIM, {
        const float sc = 0.044194173824159216f; /* 1/sqrt(512) */
        float* dst = Og + ((size_t)b * SEQ + m) * DIM + n;
        *(float2*)dst = make_float2(acc[mt][nt][0] * sc, acc[mt][nt][1] * sc);
        *(float2*)(dst + 8 * DIM) =
            make_float2(acc[mt][nt][2] * sc, acc[mt][nt][3] * sc);
    })
}

// ---------------------------------------------------------------------------
// PROVEN (R4) masked softmax, dtype-flexible valid_len
// ---------------------------------------------------------------------------
__global__ __launch_bounds__(128) void softmax_kernel(float* __restrict__ X,
                                                      const void* __restrict__ vlen_raw) {
    const int row = blockIdx.x;
    const int qi = row & (SEQ - 1);
    long long L = g_vlen_is64 ? ((const long long*)vlen_raw)[qi]
                              : (long long)((const int*)vlen_raw)[qi];
    float* xr = X + (size_t)row * DIM;
    const int t = threadIdx.x;
    const int j = t << 2;

    float4 v = *(float4*)&xr[j];
    float vals[4] = {v.x, v.y, v.z, v.w};
#pragma unroll
    for (int c = 0; c < 4; c++)
        if ((long long)(j + c) > L) vals[c] = -1000000.0f;

    __shared__ float red[4];
    const int lane = t & 31, warp = t >> 5;

    float m = fmaxf(fmaxf(vals[0], vals[1]), fmaxf(vals[2], vals[3]));
#pragma unroll
    for (int o = 16; o > 0; o >>= 1) m = fmaxf(m, __shfl_xor_sync(0xffffffffu, m, o));
    if (lane == 0) red[warp] = m;
    __syncthreads();
    m = fmaxf(fmaxf(red[0], red[1]), fmaxf(red[2], red[3]));
    __syncthreads();

    float e[4];
#pragma unroll
    for (int c = 0; c < 4; c++) e[c] = expf(vals[c] - m);
    float s = e[0] + e[1] + e[2] + e[3];
#pragma unroll
    for (int o = 16; o > 0; o >>= 1) s += __shfl_xor_sync(0xffffffffu, s, o);
    if (lane == 0) red[warp] = s;
    __syncthreads();
    s = red[0] + red[1] + red[2] + red[3];

    const float inv = 1.0f / s;
    *(float4*)&xr[j] = make_float4(e[0] * inv, e[1] * inv, e[2] * inv, e[3] * inv);
}

// ---------------------------------------------------------------------------
// Launch (dict order K, V, Q, valid_len — proven R4). Plain kernels + dyn
// smem + cudaFuncSetAttribute (R7-proven pattern).
// ---------------------------------------------------------------------------
extern "C" void kernel_launch(void* const* d_in, const int* in_sizes, int n_in,
                              void* d_out, int out_size) {
    const float* K = (const float*)d_in[0];
    const float* V = (const float*)d_in[1];
    const float* Q = (const float*)d_in[2];
    const void* vlen = d_in[3];
    float* out = (float*)d_out;
    (void)in_sizes; (void)n_in; (void)out_size;

    static bool attr_done = false;
    if (!attr_done) {
        cudaFuncSetAttribute(gemmA_tf32,
                             cudaFuncAttributeMaxDynamicSharedMemorySize, DYN_SMEM);
        cudaFuncSetAttribute(gemmB_tf32,
                             cudaFuncAttributeMaxDynamicSharedMemorySize, DYN_SMEM);
        attr_done = true;
    }

    detect_vlen_kernel<<<1, 256>>>((const unsigned long long*)vlen);
    transposeQ_kernel<<<dim3(SEQ / 32, DIM / 32, BATCH), dim3(32, 8)>>>(Q);

    // gemmA: grid (n-tiles 64 -> 8, m-tiles 128 -> 4, B)
    gemmA_tf32<<<dim3(8, 4, BATCH), 256, DYN_SMEM>>>(K, V);
    // gemmB: grid (n-tiles 8, q-tiles 16, B)
    gemmB_tf32<<<dim3(8, 16, BATCH), 256, DYN_SMEM>>>(out);

    softmax_kernel<<<BATCH * SEQ, 128>>>(out, vlen);
}

// round 15
// speedup vs baseline: 1.8931x; 1.8931x over previous
#include <cuda_runtime.h>
#include <cuda_fp16.h>
#include <cstdint>

#define BATCH 8
#define SEQ   2048
#define DIM   512

// Scratch
__device__ float g_M[BATCH * DIM * DIM];    // M = K^T V   [b][i][j]   8 MiB
__device__ float g_Qt[BATCH * DIM * SEQ];   // Q^T         [b][i][q]  32 MiB
__device__ int g_vlen_is64;

// fp16 split smem geometry (uint32 = f16x2 words, pairs of consecutive k).
// A tile: 16 k-pairs x 128 m. B tile: 16 k-pairs x 64 n. Separate h/l tiles.
// Row pads 136/72 (both % 32 == 8) -> fragment LDS bank = 8q+g+const,
// all 32 lanes distinct = conflict-free (R12-proven bank law).
#define PADA 136
#define PADB 72
#define AH_OFF 0
#define AL_OFF (16 * PADA)              // 2176
#define BH_OFF (2 * 16 * PADA)          // 4352
#define BL_OFF (BH_OFF + 16 * PADB)     // 5504
#define BUFW   (BH_OFF + 2 * 16 * PADB) // 6656 words per buffer
#define DYN_SMEM (2 * BUFW * 4)         // 53248 B -> 2 CTAs/SM

// ---------------------------------------------------------------------------
// fp16 split helpers: h = f16(x) (11-bit mantissa), l = f16(x - h).
// Products hh + hl + lh drop only ~2^-22 x*y (same budget as proven tf32 split).
// ---------------------------------------------------------------------------
__device__ __forceinline__ void pack2(float x0, float x1, uint32_t& hw, uint32_t& lw) {
    __half h0 = __float2half_rn(x0), h1 = __float2half_rn(x1);
    float l0 = x0 - __half2float(h0);
    float l1 = x1 - __half2float(h1);
    __half2 h2 = __halves2half2(h0, h1);
    __half2 l2 = __halves2half2(__float2half_rn(l0), __float2half_rn(l1));
    hw = *(uint32_t*)&h2;
    lw = *(uint32_t*)&l2;
}

__device__ __forceinline__ void mma_f16(float* c, const uint32_t* a, const uint32_t* b) {
    asm volatile(
        "mma.sync.aligned.m16n8k16.row.col.f32.f16.f16.f32 "
        "{%0,%1,%2,%3}, {%4,%5,%6,%7}, {%8,%9}, {%0,%1,%2,%3};"
        : "+f"(c[0]), "+f"(c[1]), "+f"(c[2]), "+f"(c[3])
        : "r"(a[0]), "r"(a[1]), "r"(a[2]), "r"(a[3]), "r"(b[0]), "r"(b[1]));
}

// ---------------------------------------------------------------------------
// valid_len dtype detector (int64 vs int32) — proven R4
// ---------------------------------------------------------------------------
__global__ void detect_vlen_kernel(const unsigned long long* __restrict__ v) {
    __shared__ int bad;
    if (threadIdx.x == 0) bad = 0;
    __syncthreads();
    for (int i = threadIdx.x; i < 1024; i += blockDim.x)
        if (v[i] >= 512ull) atomicOr(&bad, 1);
    __syncthreads();
    if (threadIdx.x == 0) g_vlen_is64 = bad ? 0 : 1;
}

// ---------------------------------------------------------------------------
// Q transpose: Q [B,SEQ,DIM] -> g_Qt [B,DIM,SEQ]  (32x32 smem tiles) — proven
// ---------------------------------------------------------------------------
__global__ __launch_bounds__(256) void transposeQ_kernel(const float* __restrict__ Q) {
    __shared__ float tile[32][33];
    const int b = blockIdx.z;
    const int s0 = blockIdx.x * 32, d0 = blockIdx.y * 32;
    const int tx = threadIdx.x, ty = threadIdx.y;  // (32, 8)
    const float* src = Q + ((size_t)b * SEQ + s0) * DIM + d0;
#pragma unroll
    for (int i = 0; i < 4; i++)
        tile[ty + 8 * i][tx] = src[(size_t)(ty + 8 * i) * DIM + tx];
    __syncthreads();
    float* dst = g_Qt + ((size_t)b * DIM + d0) * SEQ + s0;
#pragma unroll
    for (int i = 0; i < 4; i++)
        dst[(size_t)(ty + 8 * i) * SEQ + tx] = tile[tx][ty + 8 * i];
}

// ===========================================================================
// fp16 split GEMM body (plain kernels — R8 lesson; dyn smem + attr — proven).
//   D[m][n] = sum_k A[k][m]*B[k][n], products hh + hl + lh on m16n8k16.
//   CTA 128m x 64n, 256 threads, 8 warps (4m x 2n) of 32x32 (R14 mapping).
//   2 CTAs/SM. Double-buffered. Fill packs (h,l) f16x2 once per element.
//   Fill map: thread t -> k-pair rp=t>>4, col base c4=4*(t&15):
//     A: 2 rows x float4 at c4 and c4+64 (coalesced); B: 2 rows x float4 at c4.
// ===========================================================================
#define GEMM_BODY(NCHUNK, LDA, LDB, EPILOGUE)                                  \
    extern __shared__ uint32_t smu[];                                          \
    const int t = threadIdx.x;                                                 \
    const int wid = t >> 5, lane = t & 31;                                     \
    const int g = lane >> 2, q = lane & 3;                                     \
    const int mw = (wid >> 1) * 32;                                            \
    const int nw = (wid & 1) * 32;                                             \
    const int b = blockIdx.z;                                                  \
    const int m0 = blockIdx.y * 128;                                           \
    const int n0 = blockIdx.x * 64;                                            \
    float acc[2][4][4] = {};                                                   \
    const int rp = t >> 4, c4 = (t & 15) * 4;                                  \
    float4 pa0, pa1, pa2, pa3, pb0, pb1;                                       \
    /* LDG chunk 0 */                                                          \
    pa0 = *(const float4*)&Ab[(size_t)(2 * rp) * (LDA) + m0 + c4];             \
    pa1 = *(const float4*)&Ab[(size_t)(2 * rp) * (LDA) + m0 + c4 + 64];        \
    pa2 = *(const float4*)&Ab[(size_t)(2 * rp + 1) * (LDA) + m0 + c4];         \
    pa3 = *(const float4*)&Ab[(size_t)(2 * rp + 1) * (LDA) + m0 + c4 + 64];    \
    pb0 = *(const float4*)&Bb[(size_t)(2 * rp) * (LDB) + n0 + c4];             \
    pb1 = *(const float4*)&Bb[(size_t)(2 * rp + 1) * (LDB) + n0 + c4];         \
    /* pack + STS buffer 0 */                                                  \
    {                                                                          \
        uint32_t* bufp = smu;                                                  \
        uint4 hA, lA;                                                          \
        pack2(pa0.x, pa2.x, hA.x, lA.x); pack2(pa0.y, pa2.y, hA.y, lA.y);      \
        pack2(pa0.z, pa2.z, hA.z, lA.z); pack2(pa0.w, pa2.w, hA.w, lA.w);      \
        *(uint4*)&bufp[AH_OFF + rp * PADA + c4] = hA;                          \
        *(uint4*)&bufp[AL_OFF + rp * PADA + c4] = lA;                          \
        pack2(pa1.x, pa3.x, hA.x, lA.x); pack2(pa1.y, pa3.y, hA.y, lA.y);      \
        pack2(pa1.z, pa3.z, hA.z, lA.z); pack2(pa1.w, pa3.w, hA.w, lA.w);      \
        *(uint4*)&bufp[AH_OFF + rp * PADA + c4 + 64] = hA;                     \
        *(uint4*)&bufp[AL_OFF + rp * PADA + c4 + 64] = lA;                     \
        pack2(pb0.x, pb1.x, hA.x, lA.x); pack2(pb0.y, pb1.y, hA.y, lA.y);      \
        pack2(pb0.z, pb1.z, hA.z, lA.z); pack2(pb0.w, pb1.w, hA.w, lA.w);      \
        *(uint4*)&bufp[BH_OFF + rp * PADB + c4] = hA;                          \
        *(uint4*)&bufp[BL_OFF + rp * PADB + c4] = lA;                          \
    }                                                                          \
    __syncthreads();                                                           \
    for (int c = 0; c < (NCHUNK); c++) {                                       \
        if (c + 1 < (NCHUNK)) {                                                \
            const int kn = (c + 1) * 32;                                       \
            pa0 = *(const float4*)&Ab[(size_t)(kn + 2 * rp) * (LDA) + m0 + c4];        \
            pa1 = *(const float4*)&Ab[(size_t)(kn + 2 * rp) * (LDA) + m0 + c4 + 64];   \
            pa2 = *(const float4*)&Ab[(size_t)(kn + 2 * rp + 1) * (LDA) + m0 + c4];    \
            pa3 = *(const float4*)&Ab[(size_t)(kn + 2 * rp + 1) * (LDA) + m0 + c4 + 64]; \
            pb0 = *(const float4*)&Bb[(size_t)(kn + 2 * rp) * (LDB) + n0 + c4];        \
            pb1 = *(const float4*)&Bb[(size_t)(kn + 2 * rp + 1) * (LDB) + n0 + c4];    \
        }                                                                      \
        const uint32_t* Ah = smu + (c & 1) * BUFW + AH_OFF;                    \
        const uint32_t* Al = smu + (c & 1) * BUFW + AL_OFF;                    \
        const uint32_t* Bh = smu + (c & 1) * BUFW + BH_OFF;                    \
        const uint32_t* Bl = smu + (c & 1) * BUFW + BL_OFF;                    \
        _Pragma("unroll")                                                      \
        for (int kk = 0; kk < 2; kk++) {                                       \
            const int r0 = (8 * kk + q) * PADB, r1 = (8 * kk + q + 4) * PADB;  \
            uint32_t bh[8], bl[8];                                             \
            _Pragma("unroll")                                                  \
            for (int nt = 0; nt < 4; nt++) {                                   \
                const int nn = nw + nt * 8 + g;                                \
                bh[nt * 2]     = Bh[r0 + nn];                                  \
                bh[nt * 2 + 1] = Bh[r1 + nn];                                  \
                bl[nt * 2]     = Bl[r0 + nn];                                  \
                bl[nt * 2 + 1] = Bl[r1 + nn];                                  \
            }                                                                  \
            const int s0_ = (8 * kk + q) * PADA, s1_ = (8 * kk + q + 4) * PADA; \
            uint32_t ah[2][4], al[2][4];                                       \
            _Pragma("unroll")                                                  \
            for (int mt = 0; mt < 2; mt++) {                                   \
                const int ma = mw + mt * 16 + g;                               \
                ah[mt][0] = Ah[s0_ + ma];                                      \
                ah[mt][1] = Ah[s0_ + ma + 8];                                  \
                ah[mt][2] = Ah[s1_ + ma];                                      \
                ah[mt][3] = Ah[s1_ + ma + 8];                                  \
                al[mt][0] = Al[s0_ + ma];                                      \
                al[mt][1] = Al[s0_ + ma + 8];                                  \
                al[mt][2] = Al[s1_ + ma];                                      \
                al[mt][3] = Al[s1_ + ma + 8];                                  \
            }                                                                  \
            _Pragma("unroll")                                                  \
            for (int mt = 0; mt < 2; mt++)                                     \
                _Pragma("unroll")                                              \
                for (int nt = 0; nt < 4; nt++)                                 \
                    mma_f16(acc[mt][nt], ah[mt], &bh[nt * 2]);                 \
            _Pragma("unroll")                                                  \
            for (int mt = 0; mt < 2; mt++)                                     \
                _Pragma("unroll")                                              \
                for (int nt = 0; nt < 4; nt++)                                 \
                    mma_f16(acc[mt][nt], ah[mt], &bl[nt * 2]);                 \
            _Pragma("unroll")                                                  \
            for (int mt = 0; mt < 2; mt++)                                     \
                _Pragma("unroll")                                              \
                for (int nt = 0; nt < 4; nt++)                                 \
                    mma_f16(acc[mt][nt], al[mt], &bh[nt * 2]);                 \
        }                                                                      \
        if (c + 1 < (NCHUNK)) {                                                \
            uint32_t* bufp = smu + ((c + 1) & 1) * BUFW;                       \
            uint4 hA, lA;                                                      \
            pack2(pa0.x, pa2.x, hA.x, lA.x); pack2(pa0.y, pa2.y, hA.y, lA.y);  \
            pack2(pa0.z, pa2.z, hA.z, lA.z); pack2(pa0.w, pa2.w, hA.w, lA.w);  \
            *(uint4*)&bufp[AH_OFF + rp * PADA + c4] = hA;                      \
            *(uint4*)&bufp[AL_OFF + rp * PADA + c4] = lA;                      \
            pack2(pa1.x, pa3.x, hA.x, lA.x); pack2(pa1.y, pa3.y, hA.y, lA.y);  \
            pack2(pa1.z, pa3.z, hA.z, lA.z); pack2(pa1.w, pa3.w, hA.w, lA.w);  \
            *(uint4*)&bufp[AH_OFF + rp * PADA + c4 + 64] = hA;                 \
            *(uint4*)&bufp[AL_OFF + rp * PADA + c4 + 64] = lA;                 \
            pack2(pb0.x, pb1.x, hA.x, lA.x); pack2(pb0.y, pb1.y, hA.y, lA.y);  \
            pack2(pb0.z, pb1.z, hA.z, lA.z); pack2(pb0.w, pb1.w, hA.w, lA.w);  \
            *(uint4*)&bufp[BH_OFF + rp * PADB + c4] = hA;                      \
            *(uint4*)&bufp[BL_OFF + rp * PADB + c4] = lA;                      \
        }                                                                      \
        __syncthreads();                                                       \
    }                                                                          \
    _Pragma("unroll")                                                          \
    for (int mt = 0; mt < 2; mt++) {                                           \
        _Pragma("unroll")                                                      \
        for (int nt = 0; nt < 4; nt++) {                                       \
            const int m = m0 + mw + mt * 16 + g;                               \
            const int n = n0 + nw + nt * 8 + 2 * q;                            \
            EPILOGUE                                                           \
        }                                                                      \
    }

// ---------------------------------------------------------------------------
// gemmA: M[i][j] = sum_s K[s][i] V[s][j]    (K=2048)
// ---------------------------------------------------------------------------
__global__ __launch_bounds__(256, 2) void gemmA_f16(const float* __restrict__ Kg,
                                                    const float* __restrict__ Vg) {
    const float* Ab = Kg + (size_t)blockIdx.z * SEQ * DIM;
    const float* Bb = Vg + (size_t)blockIdx.z * SEQ * DIM;
    GEMM_BODY(SEQ / 32, DIM, DIM, {
        float* dst = g_M + (size_t)b * DIM * DIM + (size_t)m * DIM + n;
        *(float2*)dst = make_float2(acc[mt][nt][0], acc[mt][nt][1]);
        *(float2*)(dst + 8 * DIM) = make_float2(acc[mt][nt][2], acc[mt][nt][3]);
    })
}

// ---------------------------------------------------------------------------
// gemmB: X[q][j] = sum_i Qt[i][q] M[i][j] / sqrt(512)   (K=512)
// ---------------------------------------------------------------------------
__global__ __launch_bounds__(256, 2) void gemmB_f16(float* __restrict__ Og) {
    const float* Ab = g_Qt + (size_t)blockIdx.z * DIM * SEQ;
    const float* Bb = g_M + (size_t)blockIdx.z * DIM * DIM;
    GEMM_BODY(DIM / 32, SEQ, DIM, {
        const float sc = 0.044194173824159216f; /* 1/sqrt(512) */
        float* dst = Og + ((size_t)b * SEQ + m) * DIM + n;
        *(float2*)dst = make_float2(acc[mt][nt][0] * sc, acc[mt][nt][1] * sc);
        *(float2*)(dst + 8 * DIM) =
            make_float2(acc[mt][nt][2] * sc, acc[mt][nt][3] * sc);
    })
}

// ---------------------------------------------------------------------------
// PROVEN (R4) masked softmax, dtype-flexible valid_len
// ---------------------------------------------------------------------------
__global__ __launch_bounds__(128) void softmax_kernel(float* __restrict__ X,
                                                      const void* __restrict__ vlen_raw) {
    const int row = blockIdx.x;
    const int qi = row & (SEQ - 1);
    long long L = g_vlen_is64 ? ((const long long*)vlen_raw)[qi]
                              : (long long)((const int*)vlen_raw)[qi];
    float* xr = X + (size_t)row * DIM;
    const int t = threadIdx.x;
    const int j = t << 2;

    float4 v = *(float4*)&xr[j];
    float vals[4] = {v.x, v.y, v.z, v.w};
#pragma unroll
    for (int c = 0; c < 4; c++)
        if ((long long)(j + c) > L) vals[c] = -1000000.0f;

    __shared__ float red[4];
    const int lane = t & 31, warp = t >> 5;

    float m = fmaxf(fmaxf(vals[0], vals[1]), fmaxf(vals[2], vals[3]));
#pragma unroll
    for (int o = 16; o > 0; o >>= 1) m = fmaxf(m, __shfl_xor_sync(0xffffffffu, m, o));
    if (lane == 0) red[warp] = m;
    __syncthreads();
    m = fmaxf(fmaxf(red[0], red[1]), fmaxf(red[2], red[3]));
    __syncthreads();

    float e[4];
#pragma unroll
    for (int c = 0; c < 4; c++) e[c] = expf(vals[c] - m);
    float s = e[0] + e[1] + e[2] + e[3];
#pragma unroll
    for (int o = 16; o > 0; o >>= 1) s += __shfl_xor_sync(0xffffffffu, s, o);
    if (lane == 0) red[warp] = s;
    __syncthreads();
    s = red[0] + red[1] + red[2] + red[3];

    const float inv = 1.0f / s;
    *(float4*)&xr[j] = make_float4(e[0] * inv, e[1] * inv, e[2] * inv, e[3] * inv);
}

// ---------------------------------------------------------------------------
// Launch (dict order K, V, Q, valid_len — proven R4). Plain kernels + dyn
// smem + cudaFuncSetAttribute (R7/R12/R14-proven pattern).
// ---------------------------------------------------------------------------
extern "C" void kernel_launch(void* const* d_in, const int* in_sizes, int n_in,
                              void* d_out, int out_size) {
    const float* K = (const float*)d_in[0];
    const float* V = (const float*)d_in[1];
    const float* Q = (const float*)d_in[2];
    const void* vlen = d_in[3];
    float* out = (float*)d_out;
    (void)in_sizes; (void)n_in; (void)out_size;

    static bool attr_done = false;
    if (!attr_done) {
        cudaFuncSetAttribute(gemmA_f16,
                             cudaFuncAttributeMaxDynamicSharedMemorySize, DYN_SMEM);
        cudaFuncSetAttribute(gemmB_f16,
                             cudaFuncAttributeMaxDynamicSharedMemorySize, DYN_SMEM);
        attr_done = true;
    }

    detect_vlen_kernel<<<1, 256>>>((const unsigned long long*)vlen);
    transposeQ_kernel<<<dim3(SEQ / 32, DIM / 32, BATCH), dim3(32, 8)>>>(Q);

    // gemmA: grid (n-tiles 512/64=8, m-tiles 512/128=4, B)
    gemmA_f16<<<dim3(8, 4, BATCH), 256, DYN_SMEM>>>(K, V);
    // gemmB: grid (n-tiles 8, q-tiles 2048/128=16, B)
    gemmB_f16<<<dim3(8, 16, BATCH), 256, DYN_SMEM>>>(out);

    softmax_kernel<<<BATCH * SEQ, 128>>>(out, vlen);
}

// round 16
// speedup vs baseline: 1.9509x; 1.0306x over previous
#include <cuda_runtime.h>
#include <cuda_fp16.h>
#include <cstdint>

#define BATCH 8
#define SEQ   2048
#define DIM   512

// Scratch
__device__ float g_M[BATCH * DIM * DIM];    // M = K^T V   [b][i][j]   8 MiB
__device__ float g_Qt[BATCH * DIM * SEQ];   // Q^T         [b][i][q]  32 MiB
__device__ int g_vlen_is64;

// fp16 split smem geometry (uint32 = f16x2 words, pairs of consecutive k).
// A tile: 16 k-pairs x 128 m. B tile: 16 k-pairs x 64 n. Separate h/l tiles.
// Row pads 136/72 (both % 32 == 8) -> fragment LDS bank = 8q+g+const,
// all 32 lanes distinct = conflict-free (R12-proven bank law).
#define PADA 136
#define PADB 72
#define AH_OFF 0
#define AL_OFF (16 * PADA)              // 2176
#define BH_OFF (2 * 16 * PADA)          // 4352
#define BL_OFF (BH_OFF + 16 * PADB)     // 5504
#define BUFW   (BH_OFF + 2 * 16 * PADB) // 6656 words per buffer
#define DYN_SMEM (2 * BUFW * 4)         // 53248 B -> 2 CTAs/SM

// ---------------------------------------------------------------------------
// fp16 split helpers: h = f16(x) (11-bit mantissa), l = f16(x - h).
// Products hh (f32 acc) + [hl + lh] (f16 acc — small magnitudes, ~8e-5 err).
// ---------------------------------------------------------------------------
__device__ __forceinline__ void pack2(float x0, float x1, uint32_t& hw, uint32_t& lw) {
    __half h0 = __float2half_rn(x0), h1 = __float2half_rn(x1);
    float l0 = x0 - __half2float(h0);
    float l1 = x1 - __half2float(h1);
    __half2 h2 = __halves2half2(h0, h1);
    __half2 l2 = __halves2half2(__float2half_rn(l0), __float2half_rn(l1));
    hw = *(uint32_t*)&h2;
    lw = *(uint32_t*)&l2;
}

__device__ __forceinline__ void mma_f16(float* c, const uint32_t* a, const uint32_t* b) {
    asm volatile(
        "mma.sync.aligned.m16n8k16.row.col.f32.f16.f16.f32 "
        "{%0,%1,%2,%3}, {%4,%5,%6,%7}, {%8,%9}, {%0,%1,%2,%3};"
        : "+f"(c[0]), "+f"(c[1]), "+f"(c[2]), "+f"(c[3])
        : "r"(a[0]), "r"(a[1]), "r"(a[2]), "r"(a[3]), "r"(b[0]), "r"(b[1]));
}

// fp16-accumulator variant (R16 probe: potentially 2x issue rate)
__device__ __forceinline__ void mma_f16acc(uint32_t* c, const uint32_t* a,
                                           const uint32_t* b) {
    asm volatile(
        "mma.sync.aligned.m16n8k16.row.col.f16.f16.f16.f16 "
        "{%0,%1}, {%2,%3,%4,%5}, {%6,%7}, {%0,%1};"
        : "+r"(c[0]), "+r"(c[1])
        : "r"(a[0]), "r"(a[1]), "r"(a[2]), "r"(a[3]), "r"(b[0]), "r"(b[1]));
}

// ---------------------------------------------------------------------------
// valid_len dtype detector (int64 vs int32) — proven R4
// ---------------------------------------------------------------------------
__global__ void detect_vlen_kernel(const unsigned long long* __restrict__ v) {
    __shared__ int bad;
    if (threadIdx.x == 0) bad = 0;
    __syncthreads();
    for (int i = threadIdx.x; i < 1024; i += blockDim.x)
        if (v[i] >= 512ull) atomicOr(&bad, 1);
    __syncthreads();
    if (threadIdx.x == 0) g_vlen_is64 = bad ? 0 : 1;
}

// ---------------------------------------------------------------------------
// Q transpose: Q [B,SEQ,DIM] -> g_Qt [B,DIM,SEQ]  (32x32 smem tiles) — proven
// ---------------------------------------------------------------------------
__global__ __launch_bounds__(256) void transposeQ_kernel(const float* __restrict__ Q) {
    __shared__ float tile[32][33];
    const int b = blockIdx.z;
    const int s0 = blockIdx.x * 32, d0 = blockIdx.y * 32;
    const int tx = threadIdx.x, ty = threadIdx.y;  // (32, 8)
    const float* src = Q + ((size_t)b * SEQ + s0) * DIM + d0;
#pragma unroll
    for (int i = 0; i < 4; i++)
        tile[ty + 8 * i][tx] = src[(size_t)(ty + 8 * i) * DIM + tx];
    __syncthreads();
    float* dst = g_Qt + ((size_t)b * DIM + d0) * SEQ + s0;
#pragma unroll
    for (int i = 0; i < 4; i++)
        dst[(size_t)(ty + 8 * i) * SEQ + tx] = tile[tx][ty + 8 * i];
}

// ===========================================================================
// fp16 split GEMM body (R15-proven skeleton; R16 delta: low passes f16-acc).
//   D[m][n] = sum_k A[k][m]*B[k][n]:
//     pass1: hh -> f32 accumulators (m16n8k16 f32 acc)
//     pass2+3: hl, lh -> shared f16x2 accumulators (m16n8k16 f16 acc)
//   CTA 128m x 64n, 256 threads, 8 warps (4m x 2n) of 32x32. 2 CTAs/SM.
// ===========================================================================
#define GEMM_BODY(NCHUNK, LDA, LDB, EPILOGUE)                                  \
    extern __shared__ uint32_t smu[];                                          \
    const int t = threadIdx.x;                                                 \
    const int wid = t >> 5, lane = t & 31;                                     \
    const int g = lane >> 2, q = lane & 3;                                     \
    const int mw = (wid >> 1) * 32;                                            \
    const int nw = (wid & 1) * 32;                                             \
    const int b = blockIdx.z;                                                  \
    const int m0 = blockIdx.y * 128;                                           \
    const int n0 = blockIdx.x * 64;                                            \
    float acc[2][4][4] = {};                                                   \
    uint32_t accL[2][4][2] = {};                                               \
    const int rp = t >> 4, c4 = (t & 15) * 4;                                  \
    float4 pa0, pa1, pa2, pa3, pb0, pb1;                                       \
    /* LDG chunk 0 */                                                          \
    pa0 = *(const float4*)&Ab[(size_t)(2 * rp) * (LDA) + m0 + c4];             \
    pa1 = *(const float4*)&Ab[(size_t)(2 * rp) * (LDA) + m0 + c4 + 64];        \
    pa2 = *(const float4*)&Ab[(size_t)(2 * rp + 1) * (LDA) + m0 + c4];         \
    pa3 = *(const float4*)&Ab[(size_t)(2 * rp + 1) * (LDA) + m0 + c4 + 64];    \
    pb0 = *(const float4*)&Bb[(size_t)(2 * rp) * (LDB) + n0 + c4];             \
    pb1 = *(const float4*)&Bb[(size_t)(2 * rp + 1) * (LDB) + n0 + c4];         \
    /* pack + STS buffer 0 */                                                  \
    {                                                                          \
        uint32_t* bufp = smu;                                                  \
        uint4 hA, lA;                                                          \
        pack2(pa0.x, pa2.x, hA.x, lA.x); pack2(pa0.y, pa2.y, hA.y, lA.y);      \
        pack2(pa0.z, pa2.z, hA.z, lA.z); pack2(pa0.w, pa2.w, hA.w, lA.w);      \
        *(uint4*)&bufp[AH_OFF + rp * PADA + c4] = hA;                          \
        *(uint4*)&bufp[AL_OFF + rp * PADA + c4] = lA;                          \
        pack2(pa1.x, pa3.x, hA.x, lA.x); pack2(pa1.y, pa3.y, hA.y, lA.y);      \
        pack2(pa1.z, pa3.z, hA.z, lA.z); pack2(pa1.w, pa3.w, hA.w, lA.w);      \
        *(uint4*)&bufp[AH_OFF + rp * PADA + c4 + 64] = hA;                     \
        *(uint4*)&bufp[AL_OFF + rp * PADA + c4 + 64] = lA;                     \
        pack2(pb0.x, pb1.x, hA.x, lA.x); pack2(pb0.y, pb1.y, hA.y, lA.y);      \
        pack2(pb0.z, pb1.z, hA.z, lA.z); pack2(pb0.w, pb1.w, hA.w, lA.w);      \
        *(uint4*)&bufp[BH_OFF + rp * PADB + c4] = hA;                          \
        *(uint4*)&bufp[BL_OFF + rp * PADB + c4] = lA;                          \
    }                                                                          \
    __syncthreads();                                                           \
    for (int c = 0; c < (NCHUNK); c++) {                                       \
        if (c + 1 < (NCHUNK)) {                                                \
            const int kn = (c + 1) * 32;                                       \
            pa0 = *(const float4*)&Ab[(size_t)(kn + 2 * rp) * (LDA) + m0 + c4];        \
            pa1 = *(const float4*)&Ab[(size_t)(kn + 2 * rp) * (LDA) + m0 + c4 + 64];   \
            pa2 = *(const float4*)&Ab[(size_t)(kn + 2 * rp + 1) * (LDA) + m0 + c4];    \
            pa3 = *(const float4*)&Ab[(size_t)(kn + 2 * rp + 1) * (LDA) + m0 + c4 + 64]; \
            pb0 = *(const float4*)&Bb[(size_t)(kn + 2 * rp) * (LDB) + n0 + c4];        \
            pb1 = *(const float4*)&Bb[(size_t)(kn + 2 * rp + 1) * (LDB) + n0 + c4];    \
        }                                                                      \
        const uint32_t* Ah = smu + (c & 1) * BUFW + AH_OFF;                    \
        const uint32_t* Al = smu + (c & 1) * BUFW + AL_OFF;                    \
        const uint32_t* Bh = smu + (c & 1) * BUFW + BH_OFF;                    \
        const uint32_t* Bl = smu + (c & 1) * BUFW + BL_OFF;                    \
        _Pragma("unroll")                                                      \
        for (int kk = 0; kk < 2; kk++) {                                       \
            const int r0 = (8 * kk + q) * PADB, r1 = (8 * kk + q + 4) * PADB;  \
            uint32_t bh[8], bl[8];                                             \
            _Pragma("unroll")                                                  \
            for (int nt = 0; nt < 4; nt++) {                                   \
                const int nn = nw + nt * 8 + g;                                \
                bh[nt * 2]     = Bh[r0 + nn];                                  \
                bh[nt * 2 + 1] = Bh[r1 + nn];                                  \
                bl[nt * 2]     = Bl[r0 + nn];                                  \
                bl[nt * 2 + 1] = Bl[r1 + nn];                                  \
            }                                                                  \
            const int s0_ = (8 * kk + q) * PADA, s1_ = (8 * kk + q + 4) * PADA; \
            uint32_t ah[2][4], al[2][4];                                       \
            _Pragma("unroll")                                                  \
            for (int mt = 0; mt < 2; mt++) {                                   \
                const int ma = mw + mt * 16 + g;                               \
                ah[mt][0] = Ah[s0_ + ma];                                      \
                ah[mt][1] = Ah[s0_ + ma + 8];                                  \
                ah[mt][2] = Ah[s1_ + ma];                                      \
                ah[mt][3] = Ah[s1_ + ma + 8];                                  \
                al[mt][0] = Al[s0_ + ma];                                      \
                al[mt][1] = Al[s0_ + ma + 8];                                  \
                al[mt][2] = Al[s1_ + ma];                                      \
                al[mt][3] = Al[s1_ + ma + 8];                                  \
            }                                                                  \
            _Pragma("unroll")                                                  \
            for (int mt = 0; mt < 2; mt++)                                     \
                _Pragma("unroll")                                              \
                for (int nt = 0; nt < 4; nt++)                                 \
                    mma_f16(acc[mt][nt], ah[mt], &bh[nt * 2]);                 \
            _Pragma("unroll")                                                  \
            for (int mt = 0; mt < 2; mt++)                                     \
                _Pragma("unroll")                                              \
                for (int nt = 0; nt < 4; nt++)                                 \
                    mma_f16acc(accL[mt][nt], ah[mt], &bl[nt * 2]);             \
            _Pragma("unroll")                                                  \
            for (int mt = 0; mt < 2; mt++)                                     \
                _Pragma("unroll")                                              \
                for (int nt = 0; nt < 4; nt++)                                 \
                    mma_f16acc(accL[mt][nt], al[mt], &bh[nt * 2]);             \
        }                                                                      \
        if (c + 1 < (NCHUNK)) {                                                \
            uint32_t* bufp = smu + ((c + 1) & 1) * BUFW;                       \
            uint4 hA, lA;                                                      \
            pack2(pa0.x, pa2.x, hA.x, lA.x); pack2(pa0.y, pa2.y, hA.y, lA.y);  \
            pack2(pa0.z, pa2.z, hA.z, lA.z); pack2(pa0.w, pa2.w, hA.w, lA.w);  \
            *(uint4*)&bufp[AH_OFF + rp * PADA + c4] = hA;                      \
            *(uint4*)&bufp[AL_OFF + rp * PADA + c4] = lA;                      \
            pack2(pa1.x, pa3.x, hA.x, lA.x); pack2(pa1.y, pa3.y, hA.y, lA.y);  \
            pack2(pa1.z, pa3.z, hA.z, lA.z); pack2(pa1.w, pa3.w, hA.w, lA.w);  \
            *(uint4*)&bufp[AH_OFF + rp * PADA + c4 + 64] = hA;                 \
            *(uint4*)&bufp[AL_OFF + rp * PADA + c4 + 64] = lA;                 \
            pack2(pb0.x, pb1.x, hA.x, lA.x); pack2(pb0.y, pb1.y, hA.y, lA.y);  \
            pack2(pb0.z, pb1.z, hA.z, lA.z); pack2(pb0.w, pb1.w, hA.w, lA.w);  \
            *(uint4*)&bufp[BH_OFF + rp * PADB + c4] = hA;                      \
            *(uint4*)&bufp[BL_OFF + rp * PADB + c4] = lA;                      \
        }                                                                      \
        __syncthreads();                                                       \
    }                                                                          \
    /* merge f16 low accumulators into f32 accs (layout: c0,c1 row g; c2,c3 g+8) */ \
    _Pragma("unroll")                                                          \
    for (int mt = 0; mt < 2; mt++)                                             \
        _Pragma("unroll")                                                      \
        for (int nt = 0; nt < 4; nt++) {                                       \
            __half2 p0 = *(__half2*)&accL[mt][nt][0];                          \
            __half2 p1 = *(__half2*)&accL[mt][nt][1];                          \
            acc[mt][nt][0] += __half2float(__low2half(p0));                    \
            acc[mt][nt][1] += __half2float(__high2half(p0));                   \
            acc[mt][nt][2] += __half2float(__low2half(p1));                    \
            acc[mt][nt][3] += __half2float(__high2half(p1));                   \
        }                                                                      \
    _Pragma("unroll")                                                          \
    for (int mt = 0; mt < 2; mt++) {                                           \
        _Pragma("unroll")                                                      \
        for (int nt = 0; nt < 4; nt++) {                                       \
            const int m = m0 + mw + mt * 16 + g;                               \
            const int n = n0 + nw + nt * 8 + 2 * q;                            \
            EPILOGUE                                                           \
        }                                                                      \
    }

// ---------------------------------------------------------------------------
// gemmA: M[i][j] = sum_s K[s][i] V[s][j]    (K=2048)
// ---------------------------------------------------------------------------
__global__ __launch_bounds__(256, 2) void gemmA_f16(const float* __restrict__ Kg,
                                                    const float* __restrict__ Vg) {
    const float* Ab = Kg + (size_t)blockIdx.z * SEQ * DIM;
    const float* Bb = Vg + (size_t)blockIdx.z * SEQ * DIM;
    GEMM_BODY(SEQ / 32, DIM, DIM, {
        float* dst = g_M + (size_t)b * DIM * DIM + (size_t)m * DIM + n;
        *(float2*)dst = make_float2(acc[mt][nt][0], acc[mt][nt][1]);
        *(float2*)(dst + 8 * DIM) = make_float2(acc[mt][nt][2], acc[mt][nt][3]);
    })
}

// ---------------------------------------------------------------------------
// gemmB: X[q][j] = sum_i Qt[i][q] M[i][j] / sqrt(512)   (K=512)
// ---------------------------------------------------------------------------
__global__ __launch_bounds__(256, 2) void gemmB_f16(float* __restrict__ Og) {
    const float* Ab = g_Qt + (size_t)blockIdx.z * DIM * SEQ;
    const float* Bb = g_M + (size_t)blockIdx.z * DIM * DIM;
    GEMM_BODY(DIM / 32, SEQ, DIM, {
        const float sc = 0.044194173824159216f; /* 1/sqrt(512) */
        float* dst = Og + ((size_t)b * SEQ + m) * DIM + n;
        *(float2*)dst = make_float2(acc[mt][nt][0] * sc, acc[mt][nt][1] * sc);
        *(float2*)(dst + 8 * DIM) =
            make_float2(acc[mt][nt][2] * sc, acc[mt][nt][3] * sc);
    })
}

// ---------------------------------------------------------------------------
// PROVEN (R4) masked softmax, dtype-flexible valid_len
// ---------------------------------------------------------------------------
__global__ __launch_bounds__(128) void softmax_kernel(float* __restrict__ X,
                                                      const void* __restrict__ vlen_raw) {
    const int row = blockIdx.x;
    const int qi = row & (SEQ - 1);
    long long L = g_vlen_is64 ? ((const long long*)vlen_raw)[qi]
                              : (long long)((const int*)vlen_raw)[qi];
    float* xr = X + (size_t)row * DIM;
    const int t = threadIdx.x;
    const int j = t << 2;

    float4 v = *(float4*)&xr[j];
    float vals[4] = {v.x, v.y, v.z, v.w};
#pragma unroll
    for (int c = 0; c < 4; c++)
        if ((long long)(j + c) > L) vals[c] = -1000000.0f;

    __shared__ float red[4];
    const int lane = t & 31, warp = t >> 5;

    float m = fmaxf(fmaxf(vals[0], vals[1]), fmaxf(vals[2], vals[3]));
#pragma unroll
    for (int o = 16; o > 0; o >>= 1) m = fmaxf(m, __shfl_xor_sync(0xffffffffu, m, o));
    if (lane == 0) red[warp] = m;
    __syncthreads();
    m = fmaxf(fmaxf(red[0], red[1]), fmaxf(red[2], red[3]));
    __syncthreads();

    float e[4];
#pragma unroll
    for (int c = 0; c < 4; c++) e[c] = expf(vals[c] - m);
    float s = e[0] + e[1] + e[2] + e[3];
#pragma unroll
    for (int o = 16; o > 0; o >>= 1) s += __shfl_xor_sync(0xffffffffu, s, o);
    if (lane == 0) red[warp] = s;
    __syncthreads();
    s = red[0] + red[1] + red[2] + red[3];

    const float inv = 1.0f / s;
    *(float4*)&xr[j] = make_float4(e[0] * inv, e[1] * inv, e[2] * inv, e[3] * inv);
}

// ---------------------------------------------------------------------------
// Launch (dict order K, V, Q, valid_len — proven R4). Plain kernels + dyn
// smem + cudaFuncSetAttribute (R7/R12/R15-proven pattern).
// ---------------------------------------------------------------------------
extern "C" void kernel_launch(void* const* d_in, const int* in_sizes, int n_in,
                              void* d_out, int out_size) {
    const float* K = (const float*)d_in[0];
    const float* V = (const float*)d_in[1];
    const float* Q = (const float*)d_in[2];
    const void* vlen = d_in[3];
    float* out = (float*)d_out;
    (void)in_sizes; (void)n_in; (void)out_size;

    static bool attr_done = false;
    if (!attr_done) {
        cudaFuncSetAttribute(gemmA_f16,
                             cudaFuncAttributeMaxDynamicSharedMemorySize, DYN_SMEM);
        cudaFuncSetAttribute(gemmB_f16,
                             cudaFuncAttributeMaxDynamicSharedMemorySize, DYN_SMEM);
        attr_done = true;
    }

    detect_vlen_kernel<<<1, 256>>>((const unsigned long long*)vlen);
    transposeQ_kernel<<<dim3(SEQ / 32, DIM / 32, BATCH), dim3(32, 8)>>>(Q);

    // gemmA: grid (n-tiles 512/64=8, m-tiles 512/128=4, B)
    gemmA_f16<<<dim3(8, 4, BATCH), 256, DYN_SMEM>>>(K, V);
    // gemmB: grid (n-tiles 8, q-tiles 2048/128=16, B)
    gemmB_f16<<<dim3(8, 16, BATCH), 256, DYN_SMEM>>>(out);

    softmax_kernel<<<BATCH * SEQ, 128>>>(out, vlen);
}